// round 5
// baseline (speedup 1.0000x reference)
#include <cuda_runtime.h>
#include <cstddef>
#include <cstdint>

#define H    400
#define CC   4
#define NN   16
#define OO   32
#define RR   4
#define HH   (H*H)          // 160000

// Static device scratch
__device__ float g_T [(size_t)OO*CC*HH];   // 81.92 MB : T[o][c][i][j]
__device__ float g_XT[(size_t)NN*CC*HH];   // 40.96 MB : XT[n][c][j][k]
__device__ float g_rows[NN*OO*H];
__device__ float g_cols[NN*OO*H];

// ---- cp.async helpers ------------------------------------------------------
__device__ __forceinline__ void cp16(void* smem_dst, const void* gmem_src) {
    uint32_t d = (uint32_t)__cvta_generic_to_shared(smem_dst);
    asm volatile("cp.async.cg.shared.global [%0], [%1], 16;\n" :: "r"(d), "l"(gmem_src));
}
__device__ __forceinline__ void cp_commit() {
    asm volatile("cp.async.commit_group;\n");
}
template<int N>
__device__ __forceinline__ void cp_wait() {
    asm volatile("cp.async.wait_group %0;\n" :: "n"(N));
}
__device__ __forceinline__ float dot4(float4 a, float4 b) {
    return a.x*b.x + a.y*b.y + a.z*b.z + a.w*b.w;
}

// ---------------------------------------------------------------------------
// Kernel 1: T[o,c,i,j] = sum_r L[o,c,i,r]*L[o,c,j,r].  grid=(128,16), block=256
// ---------------------------------------------------------------------------
__global__ __launch_bounds__(256)
void kT(const float* __restrict__ L, float* __restrict__ T)
{
    const int s = blockIdx.x;                 // o*CC + c
    const float* Lp = L + (size_t)s * (H*RR);
    float*       Tp = T + (size_t)s * HH;

    __shared__ float sL[H*RR];
    for (int idx = threadIdx.x; idx < H*RR; idx += 256) sL[idx] = Lp[idx];
    __syncthreads();

    const int base = blockIdx.y * 625;
    for (int loc = threadIdx.x; loc < 625; loc += 256) {
        const int item = base + loc;
        const int it = item / 100;
        const int jq = item % 100;
        const int i0 = it * 4, j0 = jq * 4;

        float4 li[4], lj[4];
        #pragma unroll
        for (int d = 0; d < 4; d++) {
            li[d] = *reinterpret_cast<const float4*>(&sL[(i0 + d) * 4]);
            lj[d] = *reinterpret_cast<const float4*>(&sL[(j0 + d) * 4]);
        }
        #pragma unroll
        for (int d = 0; d < 4; d++) {
            float4 v;
            v.x = dot4(li[d], lj[0]);
            v.y = dot4(li[d], lj[1]);
            v.z = dot4(li[d], lj[2]);
            v.w = dot4(li[d], lj[3]);
            *reinterpret_cast<float4*>(&Tp[(size_t)(i0 + d) * H + j0]) = v;
        }
    }
}

// ---------------------------------------------------------------------------
// Kernel 2: per-(n,c) transpose XT[j,k] = x[k,j]
// ---------------------------------------------------------------------------
__global__ __launch_bounds__(256)
void kTrans(const float* __restrict__ X, float* __restrict__ XT)
{
    __shared__ float t[32][33];
    const int s = blockIdx.z;
    const float* src = X  + (size_t)s * HH;
    float*       dst = XT + (size_t)s * HH;

    const int j = blockIdx.x * 32 + threadIdx.x;
    #pragma unroll
    for (int m = 0; m < 32; m += 8) {
        const int k = blockIdx.y * 32 + threadIdx.y + m;
        if (k < H && j < H)
            t[threadIdx.y + m][threadIdx.x] = src[(size_t)k * H + j];
    }
    __syncthreads();
    const int k2 = blockIdx.y * 32 + threadIdx.x;
    #pragma unroll
    for (int m = 0; m < 32; m += 8) {
        const int j2 = blockIdx.x * 32 + threadIdx.y + m;
        if (j2 < H && k2 < H)
            dst[(size_t)j2 * H + k2] = t[threadIdx.x][threadIdx.y + m];
    }
}

// ---------------------------------------------------------------------------
// Kernel 3: FUSED marginals.  For block (i, half):
//   rows[n,o,i] = sum_{c,k} X [n,c,i,k]*T[o,c,i,k] (+bias)
//   cols[n,o,i] = sum_{c,k} XT[n,c,i,k]*T[o,c,i,k]     (T symmetric in i,j)
// T chunk loaded ONCE for both.  grid=(400,2), block 256.
// stage = dX[1024]f4 + dY[1024]f4 + dT[1024]f4 = 48 KB, x2 stages = 96 KB.
// ---------------------------------------------------------------------------
__global__ __launch_bounds__(256, 2)
void kMargF(const float* __restrict__ X, const float* __restrict__ XT,
            const float* __restrict__ T,
            float* __restrict__ rowsOut, float* __restrict__ colsOut,
            const float* __restrict__ bias)
{
    extern __shared__ float sm[];
    float4* s4 = reinterpret_cast<float4*>(sm);   // [2][3072] f4

    const int i    = blockIdx.x;
    const int half = blockIdx.y;
    const int tid  = threadIdx.x;
    const int ks = tid & 15;
    const int tt = tid >> 4;
    const int nt = (tt & 3) * 4;
    const int ot = (tt >> 2) * 4;

    auto issue = [&](int ch) {
        const int q0 = ch * 16;
        const int full = (ch < 6);
        const int cq = full ? 16 : 4;
        float4* dX = s4 + (ch & 1) * 3072;
        float4* dY = dX + 1024;
        float4* dT = dY + 1024;
        for (int idx = tid; idx < 64 * cq; idx += 256) {
            const int r  = full ? (idx >> 4) : (idx >> 2);
            const int q2 = full ? (idx & 15) : (idx & 3);
            const int c = r >> 4, m = r & 15;      // m = n (X,XT) or o' (T)
            const size_t off = (((size_t)(m * 4 + c)) * H + i) * H + (q0 + q2) * 4;
            cp16(&dX[r * 16 + q2], &X [off]);
            cp16(&dY[r * 16 + q2], &XT[off]);
            cp16(&dT[r * 16 + q2],
                 &T[((((size_t)(half * 16 + m)) * CC + c) * H + i) * H + (q0 + q2) * 4]);
        }
        cp_commit();
    };

    float accR[4][4] = {};
    float accC[4][4] = {};

    issue(0);
    #pragma unroll 1
    for (int ch = 0; ch < 7; ch++) {
        if (ch + 1 < 7) { issue(ch + 1); cp_wait<1>(); }
        else            { cp_wait<0>(); }
        __syncthreads();

        const int cq = (ch < 6) ? 16 : 4;
        const float4* bX = s4 + (ch & 1) * 3072;
        const float4* bY = bX + 1024;
        const float4* bT = bY + 1024;
        if (ks < cq) {
            #pragma unroll
            for (int c = 0; c < 4; c++) {
                float4 tv[4], xv[4], yv[4];
                #pragma unroll
                for (int b = 0; b < 4; b++) tv[b] = bT[(c * 16 + ot + b) * 16 + ks];
                #pragma unroll
                for (int a = 0; a < 4; a++) xv[a] = bX[(c * 16 + nt + a) * 16 + ks];
                #pragma unroll
                for (int a = 0; a < 4; a++) yv[a] = bY[(c * 16 + nt + a) * 16 + ks];
                #pragma unroll
                for (int a = 0; a < 4; a++)
                    #pragma unroll
                    for (int b = 0; b < 4; b++) {
                        accR[a][b] += dot4(xv[a], tv[b]);
                        accC[a][b] += dot4(yv[a], tv[b]);
                    }
            }
        }
        __syncthreads();
    }

    // Reduce 16 k-slices through smem: rows then cols
    float* red = sm;    // 4096 floats
    const int tt2 = tid >> 4, ab = tid & 15;
    const int a2 = ab >> 2, b2 = ab & 3;
    const int n2  = (tt2 & 3) * 4 + a2;
    const int op2 = (tt2 >> 2) * 4 + b2;
    const int o2  = half * 16 + op2;

    #pragma unroll
    for (int a = 0; a < 4; a++)
        #pragma unroll
        for (int b = 0; b < 4; b++)
            red[(tt * 16 + a * 4 + b) * 16 + ks] = accR[a][b];
    __syncthreads();
    {
        float v = 0.f;
        #pragma unroll
        for (int s2 = 0; s2 < 16; s2++) v += red[tid * 16 + s2];
        v += bias[o2];
        rowsOut[((size_t)n2 * OO + o2) * H + i] = v;
    }
    __syncthreads();
    #pragma unroll
    for (int a = 0; a < 4; a++)
        #pragma unroll
        for (int b = 0; b < 4; b++)
            red[(tt * 16 + a * 4 + b) * 16 + ks] = accC[a][b];
    __syncthreads();
    {
        float v = 0.f;
        #pragma unroll
        for (int s2 = 0; s2 < 16; s2++) v += red[tid * 16 + s2];
        colsOut[((size_t)n2 * OO + o2) * H + i] = v;
    }
}

// ---------------------------------------------------------------------------
// Kernel 4: out[n,o,i,j] = rows[n,o,i] + cols[n,o,j] - sum_c X[n,c,i,j]*T[o,c,i,j]
// grid=(400,2) : i, o-half of 16.  block 256.  7 chunks of 16(+4) quads.
// stage = dX[1024]f4 + dT[1024]f4 = 32 KB x2 = 64 KB (+1KB sr) -> 3 blocks/SM.
// Streaming stores (__stcs) keep T/X/cols resident in L2.
// ---------------------------------------------------------------------------
__global__ __launch_bounds__(256, 3)
void kOut(const float* __restrict__ X, const float* __restrict__ T,
          const float* __restrict__ rows, const float* __restrict__ cols,
          float* __restrict__ out)
{
    extern __shared__ float sm[];
    float4* s4 = reinterpret_cast<float4*>(sm);        // [2][2048] f4
    float*  sr = sm + 2 * 2048 * 4;                    // 256 floats

    const int i    = blockIdx.x;
    const int half = blockIdx.y;
    const int o0   = half * 16;
    const int tid  = threadIdx.x;

    {   // rows scalars for all (n, o') pairs
        const int n = tid >> 4, op = tid & 15;
        sr[tid] = rows[((size_t)n * OO + o0 + op) * H + i];
    }

    auto issue = [&](int ch) {
        const int q0 = ch * 16;
        const int full = (ch < 6);
        const int cq = full ? 16 : 4;
        float4* dX = s4 + (ch & 1) * 2048;
        float4* dT = dX + 1024;
        for (int idx = tid; idx < 64 * cq; idx += 256) {
            const int r  = full ? (idx >> 4) : (idx >> 2);
            const int q2 = full ? (idx & 15) : (idx & 3);
            const int c = r >> 4, m = r & 15;
            cp16(&dX[r * 16 + q2],
                 &X[(((size_t)(m * 4 + c)) * H + i) * H + (q0 + q2) * 4]);
            cp16(&dT[r * 16 + q2],
                 &T[((((size_t)(o0 + m)) * CC + c) * H + i) * H + (q0 + q2) * 4]);
        }
        cp_commit();
    };

    const int ks = tid & 15;
    const int tt = tid >> 4;
    const int nt = (tt & 3) * 4;
    const int ot = (tt >> 2) * 4;

    issue(0);
    #pragma unroll 1
    for (int ch = 0; ch < 7; ch++) {
        if (ch + 1 < 7) { issue(ch + 1); cp_wait<1>(); }
        else            { cp_wait<0>(); }
        __syncthreads();

        const int q0 = ch * 16;
        const int cq = (ch < 6) ? 16 : 4;
        const float4* bX = s4 + (ch & 1) * 2048;
        const float4* bT = bX + 1024;

        if (ks < cq) {
            #pragma unroll
            for (int ap = 0; ap < 2; ap++) {          // a-pairs {0,1},{2,3}
                float4 xa[2][4];
                #pragma unroll
                for (int d = 0; d < 2; d++)
                    #pragma unroll
                    for (int c = 0; c < 4; c++)
                        xa[d][c] = bX[(c * 16 + nt + ap * 2 + d) * 16 + ks];

                #pragma unroll
                for (int b = 0; b < 4; b++) {
                    float4 tb[4];
                    #pragma unroll
                    for (int c = 0; c < 4; c++)
                        tb[c] = bT[(c * 16 + ot + b) * 16 + ks];

                    const int o = o0 + ot + b;
                    float4 cv[2];
                    #pragma unroll
                    for (int d = 0; d < 2; d++)
                        cv[d] = __ldg(reinterpret_cast<const float4*>(
                            &cols[((size_t)(nt + ap * 2 + d) * OO + o) * H + (q0 + ks) * 4]));

                    #pragma unroll
                    for (int d = 0; d < 2; d++) {
                        const int n = nt + ap * 2 + d;
                        const float base = sr[n * 16 + ot + b];
                        float4 av;
                        av.x = base + cv[d].x;
                        av.y = base + cv[d].y;
                        av.z = base + cv[d].z;
                        av.w = base + cv[d].w;
                        #pragma unroll
                        for (int c = 0; c < 4; c++) {
                            av.x -= xa[d][c].x * tb[c].x;
                            av.y -= xa[d][c].y * tb[c].y;
                            av.z -= xa[d][c].z * tb[c].z;
                            av.w -= xa[d][c].w * tb[c].w;
                        }
                        __stcs(reinterpret_cast<float4*>(
                            &out[(((size_t)n * OO + o) * H + i) * H + (q0 + ks) * 4]), av);
                    }
                }
            }
        }
        __syncthreads();
    }
}

// ---------------------------------------------------------------------------
extern "C" void kernel_launch(void* const* d_in, const int* in_sizes, int n_in,
                              void* d_out, int out_size)
{
    const float* x    = (const float*)d_in[0];
    const float* wL   = (const float*)d_in[1];
    const float* bias = (const float*)d_in[2];
    float*       out  = (float*)d_out;

    float *Tbuf, *XTbuf, *rowsBuf, *colsBuf;
    cudaGetSymbolAddress((void**)&Tbuf,    g_T);
    cudaGetSymbolAddress((void**)&XTbuf,   g_XT);
    cudaGetSymbolAddress((void**)&rowsBuf, g_rows);
    cudaGetSymbolAddress((void**)&colsBuf, g_cols);

    const int smMarg = 2 * 3072 * sizeof(float4);              // 98304
    const int smOut  = 2 * 2048 * sizeof(float4) + 256 * 4;    // 66560
    cudaFuncSetAttribute(kMargF, cudaFuncAttributeMaxDynamicSharedMemorySize, smMarg);
    cudaFuncSetAttribute(kOut,   cudaFuncAttributeMaxDynamicSharedMemorySize, smOut);

    kT<<<dim3(OO * CC, 16), 256>>>(wL, Tbuf);
    kTrans<<<dim3(13, 13, NN * CC), dim3(32, 8)>>>(x, XTbuf);

    kMargF<<<dim3(H, 2), 256, smMarg>>>(x, XTbuf, Tbuf, rowsBuf, colsBuf, bias);

    kOut<<<dim3(H, 2), 256, smOut>>>(x, Tbuf, rowsBuf, colsBuf, out);
}

// round 6
// speedup vs baseline: 1.8643x; 1.8643x over previous
#include <cuda_runtime.h>
#include <cstddef>
#include <cstdint>

#define H    400
#define CC   4
#define NN   16
#define OO   32
#define RR   4
#define HH   (H*H)          // 160000

// Static device scratch
__device__ float g_T [(size_t)OO*CC*HH];   // 81.92 MB : T[o][c][i][j]
__device__ float g_XT[(size_t)NN*CC*HH];   // 40.96 MB : XT[n][c][j][k]
__device__ float g_rows[NN*OO*H];
__device__ float g_cols[NN*OO*H];

// ---- cp.async helpers ------------------------------------------------------
__device__ __forceinline__ void cp16(void* smem_dst, const void* gmem_src) {
    uint32_t d = (uint32_t)__cvta_generic_to_shared(smem_dst);
    asm volatile("cp.async.cg.shared.global [%0], [%1], 16;\n" :: "r"(d), "l"(gmem_src));
}
__device__ __forceinline__ void cp_commit() {
    asm volatile("cp.async.commit_group;\n");
}
template<int N>
__device__ __forceinline__ void cp_wait() {
    asm volatile("cp.async.wait_group %0;\n" :: "n"(N));
}
__device__ __forceinline__ float dot4(float4 a, float4 b) {
    return a.x*b.x + a.y*b.y + a.z*b.z + a.w*b.w;
}

// ---------------------------------------------------------------------------
// Kernel 1: T[o,c,i,j] = sum_r L[o,c,i,r]*L[o,c,j,r].  grid=(128,16), block=256
// ---------------------------------------------------------------------------
__global__ __launch_bounds__(256)
void kT(const float* __restrict__ L, float* __restrict__ T)
{
    const int s = blockIdx.x;                 // o*CC + c
    const float* Lp = L + (size_t)s * (H*RR);
    float*       Tp = T + (size_t)s * HH;

    __shared__ float sL[H*RR];
    for (int idx = threadIdx.x; idx < H*RR; idx += 256) sL[idx] = Lp[idx];
    __syncthreads();

    const int base = blockIdx.y * 625;
    for (int loc = threadIdx.x; loc < 625; loc += 256) {
        const int item = base + loc;
        const int it = item / 100;
        const int jq = item % 100;
        const int i0 = it * 4, j0 = jq * 4;

        float4 li[4], lj[4];
        #pragma unroll
        for (int d = 0; d < 4; d++) {
            li[d] = *reinterpret_cast<const float4*>(&sL[(i0 + d) * 4]);
            lj[d] = *reinterpret_cast<const float4*>(&sL[(j0 + d) * 4]);
        }
        #pragma unroll
        for (int d = 0; d < 4; d++) {
            float4 v;
            v.x = dot4(li[d], lj[0]);
            v.y = dot4(li[d], lj[1]);
            v.z = dot4(li[d], lj[2]);
            v.w = dot4(li[d], lj[3]);
            *reinterpret_cast<float4*>(&Tp[(size_t)(i0 + d) * H + j0]) = v;
        }
    }
}

// ---------------------------------------------------------------------------
// Kernel 2: per-(n,c) transpose XT[j,k] = x[k,j]
// ---------------------------------------------------------------------------
__global__ __launch_bounds__(256)
void kTrans(const float* __restrict__ X, float* __restrict__ XT)
{
    __shared__ float t[32][33];
    const int s = blockIdx.z;
    const float* src = X  + (size_t)s * HH;
    float*       dst = XT + (size_t)s * HH;

    const int j = blockIdx.x * 32 + threadIdx.x;
    #pragma unroll
    for (int m = 0; m < 32; m += 8) {
        const int k = blockIdx.y * 32 + threadIdx.y + m;
        if (k < H && j < H)
            t[threadIdx.y + m][threadIdx.x] = src[(size_t)k * H + j];
    }
    __syncthreads();
    const int k2 = blockIdx.y * 32 + threadIdx.x;
    #pragma unroll
    for (int m = 0; m < 32; m += 8) {
        const int j2 = blockIdx.x * 32 + threadIdx.y + m;
        if (j2 < H && k2 < H)
            dst[(size_t)j2 * H + k2] = t[threadIdx.x][threadIdx.y + m];
    }
}

// ---------------------------------------------------------------------------
// Kernel 3: FUSED marginals (unchanged from R5 — within model):
//   rows[n,o,i] = sum_{c,k} X [n,c,i,k]*T[o,c,i,k] (+bias)
//   cols[n,o,i] = sum_{c,k} XT[n,c,i,k]*T[o,c,i,k]
// grid=(400,2), block 256.  stage 48 KB x2 = 96 KB.
// ---------------------------------------------------------------------------
__global__ __launch_bounds__(256, 2)
void kMargF(const float* __restrict__ X, const float* __restrict__ XT,
            const float* __restrict__ T,
            float* __restrict__ rowsOut, float* __restrict__ colsOut,
            const float* __restrict__ bias)
{
    extern __shared__ float sm[];
    float4* s4 = reinterpret_cast<float4*>(sm);   // [2][3072] f4

    const int i    = blockIdx.x;
    const int half = blockIdx.y;
    const int tid  = threadIdx.x;
    const int ks = tid & 15;
    const int tt = tid >> 4;
    const int nt = (tt & 3) * 4;
    const int ot = (tt >> 2) * 4;

    auto issue = [&](int ch) {
        const int q0 = ch * 16;
        const int full = (ch < 6);
        const int cq = full ? 16 : 4;
        float4* dX = s4 + (ch & 1) * 3072;
        float4* dY = dX + 1024;
        float4* dT = dY + 1024;
        for (int idx = tid; idx < 64 * cq; idx += 256) {
            const int r  = full ? (idx >> 4) : (idx >> 2);
            const int q2 = full ? (idx & 15) : (idx & 3);
            const int c = r >> 4, m = r & 15;
            const size_t off = (((size_t)(m * 4 + c)) * H + i) * H + (q0 + q2) * 4;
            cp16(&dX[r * 16 + q2], &X [off]);
            cp16(&dY[r * 16 + q2], &XT[off]);
            cp16(&dT[r * 16 + q2],
                 &T[((((size_t)(half * 16 + m)) * CC + c) * H + i) * H + (q0 + q2) * 4]);
        }
        cp_commit();
    };

    float accR[4][4] = {};
    float accC[4][4] = {};

    issue(0);
    #pragma unroll 1
    for (int ch = 0; ch < 7; ch++) {
        if (ch + 1 < 7) { issue(ch + 1); cp_wait<1>(); }
        else            { cp_wait<0>(); }
        __syncthreads();

        const int cq = (ch < 6) ? 16 : 4;
        const float4* bX = s4 + (ch & 1) * 3072;
        const float4* bY = bX + 1024;
        const float4* bT = bY + 1024;
        if (ks < cq) {
            #pragma unroll
            for (int c = 0; c < 4; c++) {
                float4 tv[4], xv[4], yv[4];
                #pragma unroll
                for (int b = 0; b < 4; b++) tv[b] = bT[(c * 16 + ot + b) * 16 + ks];
                #pragma unroll
                for (int a = 0; a < 4; a++) xv[a] = bX[(c * 16 + nt + a) * 16 + ks];
                #pragma unroll
                for (int a = 0; a < 4; a++) yv[a] = bY[(c * 16 + nt + a) * 16 + ks];
                #pragma unroll
                for (int a = 0; a < 4; a++)
                    #pragma unroll
                    for (int b = 0; b < 4; b++) {
                        accR[a][b] += dot4(xv[a], tv[b]);
                        accC[a][b] += dot4(yv[a], tv[b]);
                    }
            }
        }
        __syncthreads();
    }

    float* red = sm;    // 4096 floats
    const int tt2 = tid >> 4, ab = tid & 15;
    const int a2 = ab >> 2, b2 = ab & 3;
    const int n2  = (tt2 & 3) * 4 + a2;
    const int op2 = (tt2 >> 2) * 4 + b2;
    const int o2  = half * 16 + op2;

    #pragma unroll
    for (int a = 0; a < 4; a++)
        #pragma unroll
        for (int b = 0; b < 4; b++)
            red[(tt * 16 + a * 4 + b) * 16 + ks] = accR[a][b];
    __syncthreads();
    {
        float v = 0.f;
        #pragma unroll
        for (int s2 = 0; s2 < 16; s2++) v += red[tid * 16 + s2];
        v += bias[o2];
        rowsOut[((size_t)n2 * OO + o2) * H + i] = v;
    }
    __syncthreads();
    #pragma unroll
    for (int a = 0; a < 4; a++)
        #pragma unroll
        for (int b = 0; b < 4; b++)
            red[(tt * 16 + a * 4 + b) * 16 + ks] = accC[a][b];
    __syncthreads();
    {
        float v = 0.f;
        #pragma unroll
        for (int s2 = 0; s2 < 16; s2++) v += red[tid * 16 + s2];
        colsOut[((size_t)n2 * OO + o2) * H + i] = v;
    }
}

// ---------------------------------------------------------------------------
// Kernel 4 (rebuilt on R4 layout): grid=(400,4) : i, o-group of 8. block 256.
// Thread = (n-pair np = tid>>5, quad q = tid&31).  4 chunks of 32(+4) quads.
// Smem stages T ONLY (32 rows x 32 quads = 16 KB, x2 = 32 KB) -> 3 blocks/SM.
// X read via direct coalesced __ldg (512B/warp, L2-shared across 4 blocks/i).
// Plain full-warp 512B stores.
// ---------------------------------------------------------------------------
__global__ __launch_bounds__(256, 3)
void kOut(const float* __restrict__ X, const float* __restrict__ T,
          const float* __restrict__ rows, const float* __restrict__ cols,
          float* __restrict__ out)
{
    extern __shared__ float sm[];
    float4* s4 = reinterpret_cast<float4*>(sm);   // [2][1024] f4 (T stages)
    float*  sr = sm + 2 * 1024 * 4;               // 128 floats

    const int i   = blockIdx.x;
    const int o0  = blockIdx.y * 8;
    const int tid = threadIdx.x;

    if (tid < 128) {
        const int n = tid >> 3, op = tid & 7;
        sr[tid] = rows[((size_t)n * OO + o0 + op) * H + i];
    }

    auto issue = [&](int ch) {
        const int q0 = ch * 32;
        const int full = (ch < 3);
        const int cq = full ? 32 : 4;
        float4* dT = s4 + (ch & 1) * 1024;
        for (int idx = tid; idx < 32 * cq; idx += 256) {
            const int r  = full ? (idx >> 5) : (idx >> 2);
            const int q2 = full ? (idx & 31) : (idx & 3);
            const int c = r >> 3, op = r & 7;
            cp16(&dT[r * 32 + q2],
                 &T[((((size_t)(o0 + op)) * CC + c) * H + i) * H + (q0 + q2) * 4]);
        }
        cp_commit();
    };

    const int np = tid >> 5;     // n-pair 0..7
    const int q  = tid & 31;     // quad lane (full-warp coalescing)
    const int n0 = np * 2;

    issue(0);
    #pragma unroll 1
    for (int ch = 0; ch < 4; ch++) {
        if (ch + 1 < 4) { issue(ch + 1); cp_wait<1>(); }
        else            { cp_wait<0>(); }
        __syncthreads();

        const int q0 = ch * 32;
        const int cq = (ch < 3) ? 32 : 4;
        const float4* bT = s4 + (ch & 1) * 1024;

        if (q < cq) {
            // X direct from gmem: 8 coalesced LDG.128 per thread
            float4 xv[2][4];
            #pragma unroll
            for (int d = 0; d < 2; d++)
                #pragma unroll
                for (int c = 0; c < 4; c++)
                    xv[d][c] = __ldg(reinterpret_cast<const float4*>(
                        &X[(((size_t)((n0 + d) * 4 + c)) * H + i) * H + (q0 + q) * 4]));

            #pragma unroll
            for (int op = 0; op < 8; op++) {
                float4 tv[4];
                #pragma unroll
                for (int c = 0; c < 4; c++) tv[c] = bT[(c * 8 + op) * 32 + q];

                const int o = o0 + op;
                float4 cv[2];
                #pragma unroll
                for (int d = 0; d < 2; d++)
                    cv[d] = __ldg(reinterpret_cast<const float4*>(
                        &cols[((size_t)(n0 + d) * OO + o) * H + (q0 + q) * 4]));

                #pragma unroll
                for (int d = 0; d < 2; d++) {
                    const int n = n0 + d;
                    const float base = sr[n * 8 + op];
                    float4 av;
                    av.x = base + cv[d].x;
                    av.y = base + cv[d].y;
                    av.z = base + cv[d].z;
                    av.w = base + cv[d].w;
                    #pragma unroll
                    for (int c = 0; c < 4; c++) {
                        av.x -= xv[d][c].x * tv[c].x;
                        av.y -= xv[d][c].y * tv[c].y;
                        av.z -= xv[d][c].z * tv[c].z;
                        av.w -= xv[d][c].w * tv[c].w;
                    }
                    *reinterpret_cast<float4*>(
                        &out[(((size_t)n * OO + o) * H + i) * H + (q0 + q) * 4]) = av;
                }
            }
        }
        __syncthreads();
    }
}

// ---------------------------------------------------------------------------
extern "C" void kernel_launch(void* const* d_in, const int* in_sizes, int n_in,
                              void* d_out, int out_size)
{
    const float* x    = (const float*)d_in[0];
    const float* wL   = (const float*)d_in[1];
    const float* bias = (const float*)d_in[2];
    float*       out  = (float*)d_out;

    float *Tbuf, *XTbuf, *rowsBuf, *colsBuf;
    cudaGetSymbolAddress((void**)&Tbuf,    g_T);
    cudaGetSymbolAddress((void**)&XTbuf,   g_XT);
    cudaGetSymbolAddress((void**)&rowsBuf, g_rows);
    cudaGetSymbolAddress((void**)&colsBuf, g_cols);

    const int smMarg = 2 * 3072 * sizeof(float4);              // 98304
    const int smOut  = 2 * 1024 * sizeof(float4) + 128 * 4;    // 33280
    cudaFuncSetAttribute(kMargF, cudaFuncAttributeMaxDynamicSharedMemorySize, smMarg);
    cudaFuncSetAttribute(kOut,   cudaFuncAttributeMaxDynamicSharedMemorySize, smOut);

    kT<<<dim3(OO * CC, 16), 256>>>(wL, Tbuf);
    kTrans<<<dim3(13, 13, NN * CC), dim3(32, 8)>>>(x, XTbuf);

    kMargF<<<dim3(H, 2), 256, smMarg>>>(x, XTbuf, Tbuf, rowsBuf, colsBuf, bias);

    kOut<<<dim3(H, 4), 256, smOut>>>(x, Tbuf, rowsBuf, colsBuf, out);
}

// round 7
// speedup vs baseline: 1.8778x; 1.0072x over previous
#include <cuda_runtime.h>
#include <cstddef>
#include <cstdint>

#define H    400
#define CC   4
#define NN   16
#define OO   32
#define RR   4
#define HH   (H*H)          // 160000

// Static device scratch
__device__ float g_T [(size_t)OO*CC*HH];   // 81.92 MB : T[o][c][i][j]
__device__ float g_XT[(size_t)NN*CC*HH];   // 40.96 MB : XT[n][c][j][k]
__device__ float g_rows[NN*OO*H];
__device__ float g_cols[NN*OO*H];

// ---- cp.async helpers ------------------------------------------------------
__device__ __forceinline__ void cp16(void* smem_dst, const void* gmem_src) {
    uint32_t d = (uint32_t)__cvta_generic_to_shared(smem_dst);
    asm volatile("cp.async.cg.shared.global [%0], [%1], 16;\n" :: "r"(d), "l"(gmem_src));
}
__device__ __forceinline__ void cp_commit() {
    asm volatile("cp.async.commit_group;\n");
}
template<int N>
__device__ __forceinline__ void cp_wait() {
    asm volatile("cp.async.wait_group %0;\n" :: "n"(N));
}
__device__ __forceinline__ float dot4(float4 a, float4 b) {
    return a.x*b.x + a.y*b.y + a.z*b.z + a.w*b.w;
}

// ---------------------------------------------------------------------------
// Kernel 1 (merged): blocks [0,2048)   : T[o,c,i,j] = sum_r L.L  (kT work)
//                    blocks [2048,...) : XT[n,c,j,k] = x[n,c,k,j] (kTrans work)
// block = 256.  Independent work overlapped in one launch.
// ---------------------------------------------------------------------------
__global__ __launch_bounds__(256)
void kPrep(const float* __restrict__ L, float* __restrict__ T,
           const float* __restrict__ X, float* __restrict__ XT)
{
    __shared__ float sL[H*RR];        // 6.4 KB (kT path); reused as tile below

    if (blockIdx.x < 2048) {
        // ---- kT path ----
        const int s  = blockIdx.x >> 4;          // o*CC + c
        const int yy = blockIdx.x & 15;
        const float* Lp = L + (size_t)s * (H*RR);
        float*       Tp = T + (size_t)s * HH;

        for (int idx = threadIdx.x; idx < H*RR; idx += 256) sL[idx] = Lp[idx];
        __syncthreads();

        const int base = yy * 625;
        for (int loc = threadIdx.x; loc < 625; loc += 256) {
            const int item = base + loc;
            const int it = item / 100;
            const int jq = item % 100;
            const int i0 = it * 4, j0 = jq * 4;

            float4 li[4], lj[4];
            #pragma unroll
            for (int d = 0; d < 4; d++) {
                li[d] = *reinterpret_cast<const float4*>(&sL[(i0 + d) * 4]);
                lj[d] = *reinterpret_cast<const float4*>(&sL[(j0 + d) * 4]);
            }
            #pragma unroll
            for (int d = 0; d < 4; d++) {
                float4 v;
                v.x = dot4(li[d], lj[0]);
                v.y = dot4(li[d], lj[1]);
                v.z = dot4(li[d], lj[2]);
                v.w = dot4(li[d], lj[3]);
                *reinterpret_cast<float4*>(&Tp[(size_t)(i0 + d) * H + j0]) = v;
            }
        }
    } else {
        // ---- kTrans path ----
        float (*t)[33] = reinterpret_cast<float (*)[33]>(sL);   // 32x33 tile
        const int b2  = blockIdx.x - 2048;
        const int s   = b2 / 169;                 // (n*4+c) slice
        const int rem = b2 % 169;
        const int by  = rem / 13;
        const int bx  = rem % 13;
        const int tx  = threadIdx.x & 31;
        const int ty  = threadIdx.x >> 5;

        const float* src = X  + (size_t)s * HH;
        float*       dst = XT + (size_t)s * HH;

        const int j = bx * 32 + tx;
        #pragma unroll
        for (int m = 0; m < 32; m += 8) {
            const int k = by * 32 + ty + m;
            if (k < H && j < H)
                t[ty + m][tx] = src[(size_t)k * H + j];
        }
        __syncthreads();
        const int k2 = by * 32 + tx;
        #pragma unroll
        for (int m = 0; m < 32; m += 8) {
            const int j2 = bx * 32 + ty + m;
            if (j2 < H && k2 < H)
                dst[(size_t)j2 * H + k2] = t[tx][ty + m];
        }
    }
}

// ---------------------------------------------------------------------------
// Kernel 2: FUSED marginals.
//   rows[n,o,i] = sum_{c,k} X [n,c,i,k]*T[o,c,i,k] (+bias)
//   cols[n,o,i] = sum_{c,k} XT[n,c,i,k]*T[o,c,i,k]
// grid=(400,2), block 256.  stage 48 KB x2 = 96 KB.
// ---------------------------------------------------------------------------
__global__ __launch_bounds__(256, 2)
void kMargF(const float* __restrict__ X, const float* __restrict__ XT,
            const float* __restrict__ T,
            float* __restrict__ rowsOut, float* __restrict__ colsOut,
            const float* __restrict__ bias)
{
    extern __shared__ float sm[];
    float4* s4 = reinterpret_cast<float4*>(sm);   // [2][3072] f4

    const int i    = blockIdx.x;
    const int half = blockIdx.y;
    const int tid  = threadIdx.x;
    const int ks = tid & 15;
    const int tt = tid >> 4;
    const int nt = (tt & 3) * 4;
    const int ot = (tt >> 2) * 4;

    auto issue = [&](int ch) {
        const int q0 = ch * 16;
        const int full = (ch < 6);
        const int cq = full ? 16 : 4;
        float4* dX = s4 + (ch & 1) * 3072;
        float4* dY = dX + 1024;
        float4* dT = dY + 1024;
        for (int idx = tid; idx < 64 * cq; idx += 256) {
            const int r  = full ? (idx >> 4) : (idx >> 2);
            const int q2 = full ? (idx & 15) : (idx & 3);
            const int c = r >> 4, m = r & 15;
            const size_t off = (((size_t)(m * 4 + c)) * H + i) * H + (q0 + q2) * 4;
            cp16(&dX[r * 16 + q2], &X [off]);
            cp16(&dY[r * 16 + q2], &XT[off]);
            cp16(&dT[r * 16 + q2],
                 &T[((((size_t)(half * 16 + m)) * CC + c) * H + i) * H + (q0 + q2) * 4]);
        }
        cp_commit();
    };

    float accR[4][4] = {};
    float accC[4][4] = {};

    issue(0);
    #pragma unroll 1
    for (int ch = 0; ch < 7; ch++) {
        if (ch + 1 < 7) { issue(ch + 1); cp_wait<1>(); }
        else            { cp_wait<0>(); }
        __syncthreads();

        const int cq = (ch < 6) ? 16 : 4;
        const float4* bX = s4 + (ch & 1) * 3072;
        const float4* bY = bX + 1024;
        const float4* bT = bY + 1024;
        if (ks < cq) {
            #pragma unroll
            for (int c = 0; c < 4; c++) {
                float4 tv[4], xv[4], yv[4];
                #pragma unroll
                for (int b = 0; b < 4; b++) tv[b] = bT[(c * 16 + ot + b) * 16 + ks];
                #pragma unroll
                for (int a = 0; a < 4; a++) xv[a] = bX[(c * 16 + nt + a) * 16 + ks];
                #pragma unroll
                for (int a = 0; a < 4; a++) yv[a] = bY[(c * 16 + nt + a) * 16 + ks];
                #pragma unroll
                for (int a = 0; a < 4; a++)
                    #pragma unroll
                    for (int b = 0; b < 4; b++) {
                        accR[a][b] += dot4(xv[a], tv[b]);
                        accC[a][b] += dot4(yv[a], tv[b]);
                    }
            }
        }
        __syncthreads();
    }

    float* red = sm;    // 4096 floats
    const int tt2 = tid >> 4, ab = tid & 15;
    const int a2 = ab >> 2, b2 = ab & 3;
    const int n2  = (tt2 & 3) * 4 + a2;
    const int op2 = (tt2 >> 2) * 4 + b2;
    const int o2  = half * 16 + op2;

    #pragma unroll
    for (int a = 0; a < 4; a++)
        #pragma unroll
        for (int b = 0; b < 4; b++)
            red[(tt * 16 + a * 4 + b) * 16 + ks] = accR[a][b];
    __syncthreads();
    {
        float v = 0.f;
        #pragma unroll
        for (int s2 = 0; s2 < 16; s2++) v += red[tid * 16 + s2];
        v += bias[o2];
        rowsOut[((size_t)n2 * OO + o2) * H + i] = v;
    }
    __syncthreads();
    #pragma unroll
    for (int a = 0; a < 4; a++)
        #pragma unroll
        for (int b = 0; b < 4; b++)
            red[(tt * 16 + a * 4 + b) * 16 + ks] = accC[a][b];
    __syncthreads();
    {
        float v = 0.f;
        #pragma unroll
        for (int s2 = 0; s2 < 16; s2++) v += red[tid * 16 + s2];
        colsOut[((size_t)n2 * OO + o2) * H + i] = v;
    }
}

// ---------------------------------------------------------------------------
// Kernel 3: identical to R6 kOut except streaming stores (__stcs).
// grid=(400,4) : i, o-group of 8. block 256.  4 chunks of 32(+4) quads.
// Smem stages T only (32 KB x2) -> 3 blocks/SM.  X via coalesced __ldg.
// ---------------------------------------------------------------------------
__global__ __launch_bounds__(256, 3)
void kOut(const float* __restrict__ X, const float* __restrict__ T,
          const float* __restrict__ rows, const float* __restrict__ cols,
          float* __restrict__ out)
{
    extern __shared__ float sm[];
    float4* s4 = reinterpret_cast<float4*>(sm);   // [2][1024] f4 (T stages)
    float*  sr = sm + 2 * 1024 * 4;               // 128 floats

    const int i   = blockIdx.x;
    const int o0  = blockIdx.y * 8;
    const int tid = threadIdx.x;

    if (tid < 128) {
        const int n = tid >> 3, op = tid & 7;
        sr[tid] = rows[((size_t)n * OO + o0 + op) * H + i];
    }

    auto issue = [&](int ch) {
        const int q0 = ch * 32;
        const int full = (ch < 3);
        const int cq = full ? 32 : 4;
        float4* dT = s4 + (ch & 1) * 1024;
        for (int idx = tid; idx < 32 * cq; idx += 256) {
            const int r  = full ? (idx >> 5) : (idx >> 2);
            const int q2 = full ? (idx & 31) : (idx & 3);
            const int c = r >> 3, op = r & 7;
            cp16(&dT[r * 32 + q2],
                 &T[((((size_t)(o0 + op)) * CC + c) * H + i) * H + (q0 + q2) * 4]);
        }
        cp_commit();
    };

    const int np = tid >> 5;     // n-pair 0..7
    const int q  = tid & 31;     // quad lane (full-warp coalescing)
    const int n0 = np * 2;

    issue(0);
    #pragma unroll 1
    for (int ch = 0; ch < 4; ch++) {
        if (ch + 1 < 4) { issue(ch + 1); cp_wait<1>(); }
        else            { cp_wait<0>(); }
        __syncthreads();

        const int q0 = ch * 32;
        const int cq = (ch < 3) ? 32 : 4;
        const float4* bT = s4 + (ch & 1) * 1024;

        if (q < cq) {
            float4 xv[2][4];
            #pragma unroll
            for (int d = 0; d < 2; d++)
                #pragma unroll
                for (int c = 0; c < 4; c++)
                    xv[d][c] = __ldg(reinterpret_cast<const float4*>(
                        &X[(((size_t)((n0 + d) * 4 + c)) * H + i) * H + (q0 + q) * 4]));

            #pragma unroll
            for (int op = 0; op < 8; op++) {
                float4 tv[4];
                #pragma unroll
                for (int c = 0; c < 4; c++) tv[c] = bT[(c * 8 + op) * 32 + q];

                const int o = o0 + op;
                float4 cv[2];
                #pragma unroll
                for (int d = 0; d < 2; d++)
                    cv[d] = __ldg(reinterpret_cast<const float4*>(
                        &cols[((size_t)(n0 + d) * OO + o) * H + (q0 + q) * 4]));

                #pragma unroll
                for (int d = 0; d < 2; d++) {
                    const int n = n0 + d;
                    const float base = sr[n * 8 + op];
                    float4 av;
                    av.x = base + cv[d].x;
                    av.y = base + cv[d].y;
                    av.z = base + cv[d].z;
                    av.w = base + cv[d].w;
                    #pragma unroll
                    for (int c = 0; c < 4; c++) {
                        av.x -= xv[d][c].x * tv[c].x;
                        av.y -= xv[d][c].y * tv[c].y;
                        av.z -= xv[d][c].z * tv[c].z;
                        av.w -= xv[d][c].w * tv[c].w;
                    }
                    __stcs(reinterpret_cast<float4*>(
                        &out[(((size_t)n * OO + o) * H + i) * H + (q0 + q) * 4]), av);
                }
            }
        }
        __syncthreads();
    }
}

// ---------------------------------------------------------------------------
extern "C" void kernel_launch(void* const* d_in, const int* in_sizes, int n_in,
                              void* d_out, int out_size)
{
    const float* x    = (const float*)d_in[0];
    const float* wL   = (const float*)d_in[1];
    const float* bias = (const float*)d_in[2];
    float*       out  = (float*)d_out;

    float *Tbuf, *XTbuf, *rowsBuf, *colsBuf;
    cudaGetSymbolAddress((void**)&Tbuf,    g_T);
    cudaGetSymbolAddress((void**)&XTbuf,   g_XT);
    cudaGetSymbolAddress((void**)&rowsBuf, g_rows);
    cudaGetSymbolAddress((void**)&colsBuf, g_cols);

    const int smMarg = 2 * 3072 * sizeof(float4);              // 98304
    const int smOut  = 2 * 1024 * sizeof(float4) + 128 * 4;    // 33280
    cudaFuncSetAttribute(kMargF, cudaFuncAttributeMaxDynamicSharedMemorySize, smMarg);
    cudaFuncSetAttribute(kOut,   cudaFuncAttributeMaxDynamicSharedMemorySize, smOut);

    // merged kT + kTrans (independent work, overlapped in one grid)
    kPrep<<<2048 + 169 * NN * CC, 256>>>(wL, Tbuf, x, XTbuf);

    kMargF<<<dim3(H, 2), 256, smMarg>>>(x, XTbuf, Tbuf, rowsBuf, colsBuf, bias);

    kOut<<<dim3(H, 4), 256, smOut>>>(x, Tbuf, rowsBuf, colsBuf, out);
}